// round 2
// baseline (speedup 1.0000x reference)
#include <cuda_runtime.h>

// Problem constants (shapes fixed by the dataset)
#define Nn   128
#define Cc   1024
#define HW   196
#define Hh   14
#define Oo   256
#define KTOP 16

// Output section offsets (float32 elements)
#define OFF_MAX  0
#define OFF_MED  524288      // 128*4096
#define OFF_ROWS 1048576     // 2*128*4096
#define OFF_COLS 1052672     // + 128*32

// Scratch (static device arrays; no allocation allowed)
__device__ float g_part[4 * Nn * HW];
__device__ float g_fre[Nn * HW];
__device__ int   g_scene[Nn * 32];
__device__ float g_nodes[2][Nn * 16 * Cc];   // [g][ (n*16+k)*1024 + c ]
__device__ float g_xbuf[2][Nn * 16 * Oo];    // [g][ (n*16+k)*256 + o ]

// ---------------------------------------------------------------------------
// 1) Channel sum, stage 1: partial sums over 256-channel chunks (deterministic)
// grid (4, 128), 224 threads
__global__ void k_sum_partial(const float* __restrict__ x) {
    int n = blockIdx.y, ch0 = blockIdx.x * 256, tid = threadIdx.x;
    if (tid >= HW) return;
    const float* base = x + (n * Cc + ch0) * HW + tid;
    float acc = 0.f;
#pragma unroll 8
    for (int c = 0; c < 256; c++) acc += base[c * HW];
    g_part[(blockIdx.x * Nn + n) * HW + tid] = acc;
}

// 1b) stage 2: combine 4 chunks
__global__ void k_reduce() {
    int i = blockIdx.x * blockDim.x + threadIdx.x;
    if (i < Nn * HW)
        g_fre[i] = (g_part[i] + g_part[Nn * HW + i]) +
                   (g_part[2 * Nn * HW + i] + g_part[3 * Nn * HW + i]);
}

// ---------------------------------------------------------------------------
// 2) Rank-based stable descending argsort; emit scene indices + rows/cols
// grid 128, 224 threads
__global__ void k_sort(float* __restrict__ out) {
    __shared__ float s[HW];
    int n = blockIdx.x, tid = threadIdx.x;
    if (tid < HW) s[tid] = g_fre[n * HW + tid];
    __syncthreads();
    if (tid >= HW) return;
    float v = s[tid];
    int r = 0;
#pragma unroll 4
    for (int j = 0; j < HW; j++) {
        float u = s[j];
        r += (u > v) || (u == v && j < tid);   // stable descending rank
    }
    int slot = -1;
    if (r < KTOP) slot = r;                       // maxK
    else if (r >= 89 && r < 89 + KTOP) slot = KTOP + (r - 89);  // medK (mstart=89)
    if (slot >= 0) {
        g_scene[n * 32 + slot] = tid;
        out[OFF_ROWS + n * 32 + slot] = (float)(tid / Hh);
        out[OFF_COLS + n * 32 + slot] = (float)(tid % Hh);
    }
}

// ---------------------------------------------------------------------------
// 3) Gather node feature vectors: coalesced SMEM staging, SMEM-side scatter
// grid (128 c-chunks of 8, 128 n), 256 threads
__global__ void k_gather(const float* __restrict__ x) {
    __shared__ float s[8 * HW];
    __shared__ int sc[32];
    int n = blockIdx.y, c0 = blockIdx.x * 8, tid = threadIdx.x;
    if (tid < 32) sc[tid] = g_scene[n * 32 + tid];
    const float* src = x + (n * Cc + c0) * HW;
    for (int i = tid; i < 8 * HW; i += 256) s[i] = src[i];
    __syncthreads();
    int cl = tid & 7, k = tid >> 3;       // 8 channels x 32 nodes
    int p = sc[k];
    float v = s[cl * HW + p];
    int g = (k >= 16);
    g_nodes[g][(n * 16 + (k & 15)) * Cc + c0 + cl] = v;
}

// ---------------------------------------------------------------------------
// 4) GEMM (2048x1024)x(1024x256)^T + BN + ReLU, fp32 SMEM-tiled
// grid (4 o-tiles, 32 m-tiles, 2 graphs), 256 threads, 64x64x16 tiles, 4x4/thread
__global__ __launch_bounds__(256) void k_gemm(
    const float* __restrict__ Wmax, const float* __restrict__ gmax,
    const float* __restrict__ bmax, const float* __restrict__ mmax,
    const float* __restrict__ vmax,
    const float* __restrict__ Wmed, const float* __restrict__ gmed,
    const float* __restrict__ bmed, const float* __restrict__ mmed,
    const float* __restrict__ vmed) {
    int g = blockIdx.z;
    const float* A  = g_nodes[g];
    const float* B  = g ? Wmed : Wmax;
    const float* gm = g ? gmed : gmax;
    const float* bt = g ? bmed : bmax;
    const float* mn = g ? mmed : mmax;
    const float* vr = g ? vmed : vmax;

    __shared__ float As[16][68];
    __shared__ float Bs[16][68];

    int tid = threadIdx.x;
    int tx = tid & 15, ty = tid >> 4;
    int m0 = blockIdx.y * 64, o0 = blockIdx.x * 64;
    int lr = tid >> 2;            // 0..63 (tile row)
    int lq = (tid & 3) * 4;       // 0,4,8,12 (k quad)
    const float* Ap = A + (m0 + lr) * Cc + lq;
    const float* Bp = B + (o0 + lr) * Cc + lq;

    float acc[4][4] = {};

    for (int kt = 0; kt < Cc; kt += 16) {
        float4 av = *(const float4*)(Ap + kt);
        float4 bv = *(const float4*)(Bp + kt);
        __syncthreads();
        As[lq + 0][lr] = av.x; As[lq + 1][lr] = av.y;
        As[lq + 2][lr] = av.z; As[lq + 3][lr] = av.w;
        Bs[lq + 0][lr] = bv.x; Bs[lq + 1][lr] = bv.y;
        Bs[lq + 2][lr] = bv.z; Bs[lq + 3][lr] = bv.w;
        __syncthreads();
#pragma unroll
        for (int k = 0; k < 16; k++) {
            float4 a = *(const float4*)&As[k][ty * 4];
            float4 b = *(const float4*)&Bs[k][tx * 4];
            acc[0][0] = fmaf(a.x, b.x, acc[0][0]);
            acc[0][1] = fmaf(a.x, b.y, acc[0][1]);
            acc[0][2] = fmaf(a.x, b.z, acc[0][2]);
            acc[0][3] = fmaf(a.x, b.w, acc[0][3]);
            acc[1][0] = fmaf(a.y, b.x, acc[1][0]);
            acc[1][1] = fmaf(a.y, b.y, acc[1][1]);
            acc[1][2] = fmaf(a.y, b.z, acc[1][2]);
            acc[1][3] = fmaf(a.y, b.w, acc[1][3]);
            acc[2][0] = fmaf(a.z, b.x, acc[2][0]);
            acc[2][1] = fmaf(a.z, b.y, acc[2][1]);
            acc[2][2] = fmaf(a.z, b.z, acc[2][2]);
            acc[2][3] = fmaf(a.z, b.w, acc[2][3]);
            acc[3][0] = fmaf(a.w, b.x, acc[3][0]);
            acc[3][1] = fmaf(a.w, b.y, acc[3][1]);
            acc[3][2] = fmaf(a.w, b.z, acc[3][2]);
            acc[3][3] = fmaf(a.w, b.w, acc[3][3]);
        }
    }

    // BN + ReLU epilogue
    int ob = o0 + tx * 4;
    float sc[4], bi[4];
#pragma unroll
    for (int j = 0; j < 4; j++) {
        float s = gm[ob + j] * rsqrtf(vr[ob + j] + 1e-5f);
        sc[j] = s;
        bi[j] = bt[ob + j] - mn[ob + j] * s;
    }
    float* X = g_xbuf[g];
#pragma unroll
    for (int i = 0; i < 4; i++) {
        int m = m0 + ty * 4 + i;
        float4 o;
        o.x = fmaxf(fmaf(acc[i][0], sc[0], bi[0]), 0.f);
        o.y = fmaxf(fmaf(acc[i][1], sc[1], bi[1]), 0.f);
        o.z = fmaxf(fmaf(acc[i][2], sc[2], bi[2]), 0.f);
        o.w = fmaxf(fmaf(acc[i][3], sc[3], bi[3]), 0.f);
        *(float4*)&X[m * Oo + ob] = o;
    }
}

// ---------------------------------------------------------------------------
// 5) Normalized adjacency (16x16) x features (16x256), both graphs, per image
// grid 128, 256 threads
__global__ void k_final(float* __restrict__ out) {
    __shared__ float sr[32], scc[32], L[2][16][16], dinv[32];
    int n = blockIdx.x, tid = threadIdx.x;
    if (tid < 32) {
        int p = g_scene[n * 32 + tid];
        sr[tid]  = (float)(p / Hh);
        scc[tid] = (float)(p % Hh);
    }
    __syncthreads();
    for (int e = tid; e < 512; e += 256) {
        int g = e >> 8, i = (e >> 4) & 15, j = e & 15, b = g * 16;
        float dr = sr[b + i] - sr[b + j];
        float dc = scc[b + i] - scc[b + j];
        L[g][i][j] = 1.f / (1.f + sqrtf(dr * dr + dc * dc));
    }
    __syncthreads();
    if (tid < 32) {
        int g = tid >> 4, i = tid & 15;
        float s = 0.f;
#pragma unroll
        for (int j = 0; j < 16; j++) s += L[g][i][j];
        dinv[tid] = rsqrtf(s);
    }
    __syncthreads();
    for (int e = tid; e < 512; e += 256) {
        int g = e >> 8, i = (e >> 4) & 15, j = e & 15;
        L[g][i][j] *= dinv[g * 16 + i] * dinv[g * 16 + j];
    }
    __syncthreads();
    int c = tid;  // 0..255
#pragma unroll
    for (int g = 0; g < 2; g++) {
        const float* X = g_xbuf[g] + n * 16 * Oo + c;
        float xv[16];
#pragma unroll
        for (int j = 0; j < 16; j++) xv[j] = X[j * Oo];
        float* O = out + (g ? OFF_MED : OFF_MAX) + n * 4096 + c;
#pragma unroll
        for (int i = 0; i < 16; i++) {
            float acc = 0.f;
#pragma unroll
            for (int j = 0; j < 16; j++) acc = fmaf(L[g][i][j], xv[j], acc);
            O[i * Oo] = acc;
        }
    }
}

// ---------------------------------------------------------------------------
extern "C" void kernel_launch(void* const* d_in, const int* in_sizes, int n_in,
                              void* d_out, int out_size) {
    const float* x = (const float*)d_in[0];
    // d_in[1] = resnet_output (unused by reference)
    const float* w_max = (const float*)d_in[2];
    const float* gmax  = (const float*)d_in[3];
    const float* bmax  = (const float*)d_in[4];
    const float* mmax  = (const float*)d_in[5];
    const float* vmax  = (const float*)d_in[6];
    const float* w_med = (const float*)d_in[7];
    const float* gmed  = (const float*)d_in[8];
    const float* bmed  = (const float*)d_in[9];
    const float* mmed  = (const float*)d_in[10];
    const float* vmed  = (const float*)d_in[11];
    float* out = (float*)d_out;

    k_sum_partial<<<dim3(4, 128), 224>>>(x);
    k_reduce<<<(Nn * HW + 255) / 256, 256>>>();
    k_sort<<<128, 224>>>(out);
    k_gather<<<dim3(128, 128), 256>>>(x);
    k_gemm<<<dim3(4, 32, 2), 256>>>(w_max, gmax, bmax, mmax, vmax,
                                    w_med, gmed, bmed, mmed, vmed);
    k_final<<<128, 256>>>(out);
}

// round 6
// speedup vs baseline: 1.6773x; 1.6773x over previous
#include <cuda_runtime.h>
#include <cuda_bf16.h>
#include <cstdint>

// Problem constants
#define Nn   128
#define Cc   1024
#define HW   196
#define Hh   14
#define Oo   256
#define KTOP 16

// Output offsets (float32 elements)
#define OFF_MAX  0
#define OFF_MED  524288
#define OFF_ROWS 1048576
#define OFF_COLS 1052672

// GEMM: logical K = 3072 (3 segments of 1024: hi*hi, hi*lo, lo*hi), chunk 64
#define NIT 48

// Scratch
__device__ float g_part[4 * Nn * HW];
__device__ float g_fre[Nn * HW];
__device__ int   g_scene[Nn * 32];
__device__ __nv_bfloat16 g_Abf[2][2048 * 2048];  // [g][m][c]: [0,1024)=hi, [1024,2048)=lo
__device__ __nv_bfloat16 g_Bbf[2][256 * 2048];   // [g][o][c]: hi | lo
__device__ float g_xbuf[2][2048 * 256];          // BN+ReLU'd GEMM output

// ---------------------------------------------------------------------------
__device__ __forceinline__ uint32_t smem_u32(const void* p) {
    uint32_t a;
    asm("{ .reg .u64 t; cvta.to.shared.u64 t, %1; cvt.u32.u64 %0, t; }" : "=r"(a) : "l"(p));
    return a;
}

#define CP_ASYNC16(dst, src) \
    asm volatile("cp.async.cg.shared.global [%0], [%1], 16;" :: "r"(dst), "l"(src) : "memory")
#define CP_COMMIT() asm volatile("cp.async.commit_group;" ::: "memory")
#define CP_WAIT(n)  asm volatile("cp.async.wait_group %0;" :: "n"(n) : "memory")

#define LDSM_X4(r, addr)                                                     \
    asm volatile("ldmatrix.sync.aligned.m8n8.x4.shared.b16 {%0,%1,%2,%3}, [%4];" \
        : "=r"((r)[0]), "=r"((r)[1]), "=r"((r)[2]), "=r"((r)[3]) : "r"(addr))

#define MMA_BF16(d, a, b0, b1)                                               \
    asm volatile("mma.sync.aligned.m16n8k16.row.col.f32.bf16.bf16.f32 "      \
        "{%0,%1,%2,%3},{%4,%5,%6,%7},{%8,%9},{%0,%1,%2,%3};"                 \
        : "+f"((d)[0]), "+f"((d)[1]), "+f"((d)[2]), "+f"((d)[3])             \
        : "r"((a)[0]), "r"((a)[1]), "r"((a)[2]), "r"((a)[3]),                \
          "r"(b0), "r"(b1))

__device__ __forceinline__ uint32_t pack2(float v0, float v1, float& r0, float& r1) {
    __nv_bfloat16 h0 = __float2bfloat16(v0);
    __nv_bfloat16 h1 = __float2bfloat16(v1);
    r0 = v0 - __bfloat162float(h0);
    r1 = v1 - __bfloat162float(h1);
    return (uint32_t)__bfloat16_as_ushort(h0) |
           ((uint32_t)__bfloat16_as_ushort(h1) << 16);
}

// ---------------------------------------------------------------------------
// 1) Channel sum (deterministic 2-stage)
__global__ void k_sum_partial(const float* __restrict__ x) {
    int n = blockIdx.y, ch0 = blockIdx.x * 256, tid = threadIdx.x;
    if (tid >= HW) return;
    const float* base = x + (n * Cc + ch0) * HW + tid;
    float acc = 0.f;
#pragma unroll 8
    for (int c = 0; c < 256; c++) acc += base[c * HW];
    g_part[(blockIdx.x * Nn + n) * HW + tid] = acc;
}

__global__ void k_reduce() {
    int i = blockIdx.x * blockDim.x + threadIdx.x;
    if (i < Nn * HW)
        g_fre[i] = (g_part[i] + g_part[Nn * HW + i]) +
                   (g_part[2 * Nn * HW + i] + g_part[3 * Nn * HW + i]);
}

// ---------------------------------------------------------------------------
// 2) Stable descending rank-sort
__global__ void k_sort(float* __restrict__ out) {
    __shared__ float s[HW];
    int n = blockIdx.x, tid = threadIdx.x;
    if (tid < HW) s[tid] = g_fre[n * HW + tid];
    __syncthreads();
    if (tid >= HW) return;
    float v = s[tid];
    int r = 0;
#pragma unroll 4
    for (int j = 0; j < HW; j++) {
        float u = s[j];
        r += (u > v) || (u == v && j < tid);
    }
    int slot = -1;
    if (r < KTOP) slot = r;
    else if (r >= 89 && r < 89 + KTOP) slot = KTOP + (r - 89);
    if (slot >= 0) {
        g_scene[n * 32 + slot] = tid;
        out[OFF_ROWS + n * 32 + slot] = (float)(tid / Hh);
        out[OFF_COLS + n * 32 + slot] = (float)(tid % Hh);
    }
}

// ---------------------------------------------------------------------------
// 3) Gather + split-bf16. grid (32 c-chunks of 32ch, 128 n), 256 thr
__global__ void k_gather(const float* __restrict__ x) {
    __shared__ float s[32 * HW];
    __shared__ int sc[32];
    int n = blockIdx.y, c0 = blockIdx.x * 32, tid = threadIdx.x;
    if (tid < 32) sc[tid] = g_scene[n * 32 + tid];
    const float4* src = (const float4*)(x + (n * Cc + c0) * HW);
    float4* s4 = (float4*)s;
#pragma unroll
    for (int i = 0; i < 7; i++) {
        int j = tid + i * 256;
        if (j < 32 * HW / 4) s4[j] = src[j];
    }
    __syncthreads();
    int k = tid >> 3, cp0 = tid & 7;
    int p = sc[k], g = k >> 4;
    int row = n * 16 + (k & 15);
    uint32_t* Ahi = (uint32_t*)(g_Abf[g] + row * 2048 + c0);
    uint32_t* Alo = (uint32_t*)(g_Abf[g] + row * 2048 + 1024 + c0);
#pragma unroll
    for (int t = 0; t < 2; t++) {
        int cp = cp0 + t * 8;
        int cl = cp * 2;
        float v0 = s[cl * HW + p], v1 = s[(cl + 1) * HW + p];
        float r0, r1, d0, d1;
        uint32_t hi = pack2(v0, v1, r0, r1);
        uint32_t lo = pack2(r0, r1, d0, d1);
        Ahi[cp] = hi;
        Alo[cp] = lo;
    }
}

// ---------------------------------------------------------------------------
// 3b) Weight split-bf16 prep. grid 1024, 256 thr
__global__ void k_prepw(const float* __restrict__ wmax, const float* __restrict__ wmed) {
    int idx = blockIdx.x * 256 + threadIdx.x;
    int cp = idx & 511, o = (idx >> 9) & 255, g = idx >> 17;
    const float* W = g ? wmed : wmax;
    float v0 = W[o * 1024 + 2 * cp], v1 = W[o * 1024 + 2 * cp + 1];
    float r0, r1, d0, d1;
    uint32_t hi = pack2(v0, v1, r0, r1);
    uint32_t lo = pack2(r0, r1, d0, d1);
    uint32_t* row = (uint32_t*)(g_Bbf[g] + o * 2048);
    row[cp] = hi;
    row[512 + cp] = lo;
}

// ---------------------------------------------------------------------------
// 4) mma.sync bf16 GEMM. Block tile 128x64, warp tile 32x32, K-chunk 64,
//    cp.async double-buffered. grid (4 ntiles, 16 mtiles, 2 graphs), 256 thr.
// SMEM layout (dynamic, bytes): A0[0,18432) B0[18432,27648) A1[27648,46080)
//   B1[46080,55296) sc[55296,55552) bi[55552,55808)
#define SMEM_GEMM 55808
#define ROWB 144   // padded row stride in bytes (72 bf16): conflict-free ldmatrix

__global__ __launch_bounds__(256) void k_gemm(
    const float* __restrict__ gmax, const float* __restrict__ bmax,
    const float* __restrict__ mmax, const float* __restrict__ vmax,
    const float* __restrict__ gmed, const float* __restrict__ bmed,
    const float* __restrict__ mmed, const float* __restrict__ vmed) {
    extern __shared__ char smem[];
    uint32_t sb = smem_u32(smem);
    int tid = threadIdx.x, lane = tid & 31, w = tid >> 5;
    int g = blockIdx.z, m0 = blockIdx.y * 128, o0 = blockIdx.x * 64;
    const __nv_bfloat16* Ab = g_Abf[g];
    const __nv_bfloat16* Bb = g_Bbf[g];

    const uint32_t A_OFF[2] = {0u, 27648u};
    const uint32_t B_OFF[2] = {18432u, 46080u};
    float* s_sc = (float*)(smem + 55296);
    float* s_bi = (float*)(smem + 55552);

    if (tid < 64) {
        const float* gm = g ? gmed : gmax;
        const float* bt = g ? bmed : bmax;
        const float* mn = g ? mmed : mmax;
        const float* vr = g ? vmed : vmax;
        int o = o0 + tid;
        float s = gm[o] * rsqrtf(vr[o] + 1e-5f);
        s_sc[tid] = s;
        s_bi[tid] = bt[o] - mn[o] * s;
    }

    int ar = tid >> 3, ach = tid & 7;   // load indexing reused per chunk

    // issue loads for chunk 'it' into buffer it&1
    auto issue = [&](int it) {
        int st = it & 1;
        int k0 = it * 64, seg = k0 >> 10, kk = k0 & 1023;
        int acol = (seg == 2) ? (1024 + kk) : kk;   // segs: hi, hi, lo
        int bcol = (seg == 1) ? (1024 + kk) : kk;   // segs: hi, lo, hi
#pragma unroll
        for (int i = 0; i < 4; i++) {
            int r = ar + i * 32;
            uint32_t dst = sb + A_OFF[st] + r * ROWB + ach * 16;
            CP_ASYNC16(dst, (const void*)(Ab + (m0 + r) * 2048 + acol + ach * 8));
        }
#pragma unroll
        for (int i = 0; i < 2; i++) {
            int r = ar + i * 32;
            uint32_t dst = sb + B_OFF[st] + r * ROWB + ach * 16;
            CP_ASYNC16(dst, (const void*)(Bb + (o0 + r) * 2048 + bcol + ach * 8));
        }
        CP_COMMIT();
    };

    int wm = (w >> 1) * 32, wn = (w & 1) * 32;
    float acc[2][4][4] = {};

    issue(0);
    for (int it = 0; it < NIT; it++) {
        int st = it & 1;
        if (it + 1 < NIT) { issue(it + 1); CP_WAIT(1); }
        else               { CP_WAIT(0); }
        __syncthreads();
        uint32_t abase = sb + A_OFF[st];
        uint32_t bbase = sb + B_OFF[st];
#pragma unroll
        for (int ks = 0; ks < 4; ks++) {
            uint32_t a[2][4], b[2][4];
#pragma unroll
            for (int mi = 0; mi < 2; mi++) {
                uint32_t addr = abase + (wm + mi * 16 + (lane & 15)) * ROWB +
                                ks * 32 + (lane >> 4) * 16;
                LDSM_X4(a[mi], addr);
            }
#pragma unroll
            for (int nj = 0; nj < 2; nj++) {
                uint32_t addr = bbase +
                    (wn + nj * 16 + (lane & 7) + ((lane >> 4) & 1) * 8) * ROWB +
                    ks * 32 + ((lane >> 3) & 1) * 16;
                LDSM_X4(b[nj], addr);
            }
#pragma unroll
            for (int mi = 0; mi < 2; mi++)
#pragma unroll
                for (int ni = 0; ni < 4; ni++)
                    MMA_BF16(acc[mi][ni], a[mi],
                             b[ni >> 1][(ni & 1) * 2], b[ni >> 1][(ni & 1) * 2 + 1]);
        }
        __syncthreads();
    }

    // Epilogue: BN + ReLU, store to g_xbuf
    int t4r = lane >> 2, t4c = (lane & 3) * 2;
    float* X = g_xbuf[g];
#pragma unroll
    for (int mi = 0; mi < 2; mi++) {
#pragma unroll
        for (int ni = 0; ni < 4; ni++) {
            int lc = wn + ni * 8 + t4c;
            int row = m0 + wm + mi * 16 + t4r;
            int col = o0 + lc;
            float sc0 = s_sc[lc], sc1 = s_sc[lc + 1];
            float bi0 = s_bi[lc], bi1 = s_bi[lc + 1];
            float2 v;
            v.x = fmaxf(fmaf(acc[mi][ni][0], sc0, bi0), 0.f);
            v.y = fmaxf(fmaf(acc[mi][ni][1], sc1, bi1), 0.f);
            *(float2*)&X[row * Oo + col] = v;
            v.x = fmaxf(fmaf(acc[mi][ni][2], sc0, bi0), 0.f);
            v.y = fmaxf(fmaf(acc[mi][ni][3], sc1, bi1), 0.f);
            *(float2*)&X[(row + 8) * Oo + col] = v;
        }
    }
}

// ---------------------------------------------------------------------------
// 5) Normalized adjacency x features. grid 128, 256 thr
__global__ void k_final(float* __restrict__ out) {
    __shared__ float sr[32], scc[32], L[2][16][16], dinv[32];
    int n = blockIdx.x, tid = threadIdx.x;
    if (tid < 32) {
        int p = g_scene[n * 32 + tid];
        sr[tid]  = (float)(p / Hh);
        scc[tid] = (float)(p % Hh);
    }
    __syncthreads();
    for (int e = tid; e < 512; e += 256) {
        int g = e >> 8, i = (e >> 4) & 15, j = e & 15, b = g * 16;
        float dr = sr[b + i] - sr[b + j];
        float dc = scc[b + i] - scc[b + j];
        L[g][i][j] = 1.f / (1.f + sqrtf(dr * dr + dc * dc));
    }
    __syncthreads();
    if (tid < 32) {
        int g = tid >> 4, i = tid & 15;
        float s = 0.f;
#pragma unroll
        for (int j = 0; j < 16; j++) s += L[g][i][j];
        dinv[tid] = rsqrtf(s);
    }
    __syncthreads();
    for (int e = tid; e < 512; e += 256) {
        int g = e >> 8, i = (e >> 4) & 15, j = e & 15;
        L[g][i][j] *= dinv[g * 16 + i] * dinv[g * 16 + j];
    }
    __syncthreads();
    int c = tid;  // 0..255
#pragma unroll
    for (int g = 0; g < 2; g++) {
        const float* X = g_xbuf[g] + n * 16 * Oo + c;
        float xv[16];
#pragma unroll
        for (int j = 0; j < 16; j++) xv[j] = X[j * Oo];
        float* O = out + (g ? OFF_MED : OFF_MAX) + n * 4096 + c;
#pragma unroll
        for (int i = 0; i < 16; i++) {
            float acc = 0.f;
#pragma unroll
            for (int j = 0; j < 16; j++) acc = fmaf(L[g][i][j], xv[j], acc);
            O[i * Oo] = acc;
        }
    }
}

// ---------------------------------------------------------------------------
extern "C" void kernel_launch(void* const* d_in, const int* in_sizes, int n_in,
                              void* d_out, int out_size) {
    const float* x     = (const float*)d_in[0];
    const float* w_max = (const float*)d_in[2];
    const float* gmax  = (const float*)d_in[3];
    const float* bmax  = (const float*)d_in[4];
    const float* mmax  = (const float*)d_in[5];
    const float* vmax  = (const float*)d_in[6];
    const float* w_med = (const float*)d_in[7];
    const float* gmed  = (const float*)d_in[8];
    const float* bmed  = (const float*)d_in[9];
    const float* mmed  = (const float*)d_in[10];
    const float* vmed  = (const float*)d_in[11];
    float* out = (float*)d_out;

    cudaFuncSetAttribute(k_gemm, cudaFuncAttributeMaxDynamicSharedMemorySize,
                         SMEM_GEMM);

    k_sum_partial<<<dim3(4, 128), 224>>>(x);
    k_reduce<<<(Nn * HW + 255) / 256, 256>>>();
    k_sort<<<128, 224>>>(out);
    k_prepw<<<1024, 256>>>(w_max, w_med);
    k_gather<<<dim3(32, 128), 256>>>(x);
    k_gemm<<<dim3(4, 16, 2), 256, SMEM_GEMM>>>(gmax, bmax, mmax, vmax,
                                               gmed, bmed, mmed, vmed);
    k_final<<<128, 256>>>(out);
}